// round 1
// baseline (speedup 1.0000x reference)
#include <cuda_runtime.h>

#define NN 100000
#define NH 20000
#define NE 1600000
#define DD 128
#define HH 512

// ---------------- scratch (device globals; no allocation allowed) ----------------
__device__ __align__(16) float g_deg_node[NN];
__device__ __align__(16) float g_deg_he[NH];
__device__ __align__(16) float g_hyper_acc[NH * DD];   // segment_sum(msg, dst)
__device__ __align__(16) float g_hyper_msg[NH * DD];   // ((acc*ch)@W1+b1)*ch
__device__ __align__(16) float g_node_acc[NN * DD];    // segment_sum(msg2, src)

// ---------------- packed fp32x2 helpers (Blackwell fma.rn.f32x2) ----------------
__device__ __forceinline__ unsigned long long f2_pack(float x, float y) {
    unsigned long long r;
    asm("mov.b64 %0, {%1, %2};" : "=l"(r) : "f"(x), "f"(y));
    return r;
}
__device__ __forceinline__ void f2_unpack(unsigned long long v, float& x, float& y) {
    asm("mov.b64 {%0, %1}, %2;" : "=f"(x), "=f"(y) : "l"(v));
}
__device__ __forceinline__ unsigned long long ffma2(unsigned long long a,
                                                    unsigned long long b,
                                                    unsigned long long c) {
    unsigned long long d;
    asm("fma.rn.f32x2 %0, %1, %2, %3;" : "=l"(d) : "l"(a), "l"(b), "l"(c));
    return d;
}

// 4 rows x 8 cols (4 f32x2 pairs) register tile, K=128.
// a_base: smem row base for this thread's 4 rows (stride a_stride, padded odd).
// w_base: smem weights as u64 pairs, row stride 64 pairs (=128 floats).
// cp0: this thread's first col-pair.
__device__ __forceinline__ void gemm_tile_k128(const float* __restrict__ a_base, int a_stride,
                                               const unsigned long long* __restrict__ w_base,
                                               int cp0, unsigned long long acc[4][4]) {
#pragma unroll 8
    for (int k = 0; k < 128; k++) {
        unsigned long long A[4];
#pragma unroll
        for (int i = 0; i < 4; i++) {
            float a = a_base[i * a_stride + k];
            A[i] = f2_pack(a, a);
        }
        unsigned long long w[4];
#pragma unroll
        for (int p = 0; p < 4; p++) w[p] = w_base[k * 64 + cp0 + p];
#pragma unroll
        for (int i = 0; i < 4; i++)
#pragma unroll
            for (int p = 0; p < 4; p++) acc[i][p] = ffma2(A[i], w[p], acc[i][p]);
    }
}

// ---------------- K0: zero scratch ----------------
__global__ void k_zero() {
    int idx = blockIdx.x * blockDim.x + threadIdx.x;
    int nthr = gridDim.x * blockDim.x;
    float4 z = make_float4(0.f, 0.f, 0.f, 0.f);
    for (int i = idx; i < NN * DD / 4; i += nthr) ((float4*)g_node_acc)[i] = z;
    for (int i = idx; i < NH * DD / 4; i += nthr) ((float4*)g_hyper_acc)[i] = z;
    for (int i = idx; i < NN; i += nthr) g_deg_node[i] = 0.f;
    for (int i = idx; i < NH; i += nthr) g_deg_he[i] = 0.f;
}

// ---------------- K1: degrees ----------------
__global__ void k_deg(const int* __restrict__ src, const int* __restrict__ dst) {
    int e = blockIdx.x * blockDim.x + threadIdx.x;
    if (e < NE) {
        atomicAdd(&g_deg_node[src[e]], 1.f);
        atomicAdd(&g_deg_he[dst[e]], 1.f);
    }
}

// ---------------- K2: scatter node -> hyper (msg = (h*cn)[src], segsum over dst) ----
__global__ void k_scatter1(const float* __restrict__ h, const int* __restrict__ src,
                           const int* __restrict__ dst) {
    int e = blockIdx.x * 8 + (threadIdx.x >> 5);
    if (e >= NE) return;
    int lane = threadIdx.x & 31;
    int s = __ldg(&src[e]);
    int d = __ldg(&dst[e]);
    float cn = rsqrtf(fmaxf(g_deg_node[s], 1.f));
    float4 v = __ldg(&((const float4*)h)[s * 32 + lane]);
    v.x *= cn; v.y *= cn; v.z *= cn; v.w *= cn;
    float* p = &g_hyper_acc[d * DD + lane * 4];
    asm volatile("red.global.add.v4.f32 [%0], {%1, %2, %3, %4};"
                 :: "l"(p), "f"(v.x), "f"(v.y), "f"(v.z), "f"(v.w) : "memory");
}

// ---------------- K3: hyper GEMM: g_hyper_msg = ((acc*ch)@W1 + b1)*ch ----------------
// = ch^2 * (acc@W1) + ch*b1
__global__ void k_gemm1(const float* __restrict__ W1, const float* __restrict__ b1) {
    extern __shared__ float sm[];
    float* sA = sm;                    // 64 x 129
    float* sW = sA + 64 * 129;         // 128 x 128
    float* sCh = sW + 128 * 128;       // 64
    const int tid = threadIdx.x;
    const int row0 = blockIdx.x * 64;

    if (tid < 64) {
        int r = row0 + tid;
        sCh[tid] = (r < NH) ? rsqrtf(fmaxf(g_deg_he[r], 1.f)) : 0.f;
    }
    for (int i = tid * 4; i < 64 * DD; i += 1024) {
        int r = i >> 7, c = i & 127;
        float4 v = make_float4(0.f, 0.f, 0.f, 0.f);
        if (row0 + r < NH) v = *(const float4*)&g_hyper_acc[(row0 + r) * DD + c];
        float* dstp = &sA[r * 129 + c];
        dstp[0] = v.x; dstp[1] = v.y; dstp[2] = v.z; dstp[3] = v.w;
    }
    for (int i = tid * 4; i < DD * DD; i += 1024)
        *(float4*)&sW[i] = *(const float4*)&W1[i];
    __syncthreads();

    const int rt = tid & 15, ct = tid >> 4;
    const int r0 = rt * 4, c0 = ct * 8, cp0 = c0 >> 1;
    const unsigned long long* sWu = (const unsigned long long*)sW;
    unsigned long long acc[4][4];
#pragma unroll
    for (int i = 0; i < 4; i++)
#pragma unroll
        for (int p = 0; p < 4; p++) acc[i][p] = 0ull;

    gemm_tile_k128(&sA[r0 * 129], 129, sWu, cp0, acc);

#pragma unroll
    for (int i = 0; i < 4; i++) {
        int gr = row0 + r0 + i;
        if (gr >= NH) continue;
        float ch = sCh[r0 + i];
        float ch2 = ch * ch;
#pragma unroll
        for (int p = 0; p < 4; p++) {
            float x, y;
            f2_unpack(acc[i][p], x, y);
            int c = c0 + 2 * p;
            float2 o;
            o.x = x * ch2 + __ldg(&b1[c]) * ch;
            o.y = y * ch2 + __ldg(&b1[c + 1]) * ch;
            *(float2*)&g_hyper_msg[gr * DD + c] = o;
        }
    }
}

// ---------------- K4: scatter hyper -> node ----------------
__global__ void k_scatter2(const int* __restrict__ src, const int* __restrict__ dst) {
    int e = blockIdx.x * 8 + (threadIdx.x >> 5);
    if (e >= NE) return;
    int lane = threadIdx.x & 31;
    int s = __ldg(&src[e]);
    int d = __ldg(&dst[e]);
    float4 v = __ldg(&((const float4*)g_hyper_msg)[d * 32 + lane]);
    float* p = &g_node_acc[s * DD + lane * 4];
    asm volatile("red.global.add.v4.f32 [%0], {%1, %2, %3, %4};"
                 :: "l"(p), "f"(v.x), "f"(v.y), "f"(v.z), "f"(v.w) : "memory");
}

// ---------------- K5: fused GEMM2 + resid + LN1 + FFN + resid + LN2 ----------------
// smem: sA[64*129] (h1), sH[64*513] (acc-in / hid / pre-LN2), sW[128*128], sCn[64]
__global__ void k_fused(const float* __restrict__ h, const float* __restrict__ W2,
                        const float* __restrict__ b2, const float* __restrict__ W3,
                        const float* __restrict__ b3, const float* __restrict__ W4,
                        const float* __restrict__ b4, const float* __restrict__ g1,
                        const float* __restrict__ be1, const float* __restrict__ g2,
                        const float* __restrict__ be2, float* __restrict__ out) {
    extern __shared__ float sm[];
    float* sA = sm;                      // 64 x 129
    float* sH = sA + 64 * 129;           // 64 x 513
    float* sW = sH + 64 * 513;           // 128 x 128
    float* sCn = sW + 128 * 128;         // 64
    const int tid = threadIdx.x;
    const int row0 = blockIdx.x * 64;
    const int warp = tid >> 5, lane = tid & 31;

    if (tid < 64) {
        int r = row0 + tid;
        sCn[tid] = (r < NN) ? rsqrtf(fmaxf(g_deg_node[r], 1.f)) : 0.f;
    }
    // node_acc -> sH (stride 513)
    for (int i = tid * 4; i < 64 * DD; i += 1024) {
        int r = i >> 7, c = i & 127;
        float4 v = make_float4(0.f, 0.f, 0.f, 0.f);
        if (row0 + r < NN) v = *(const float4*)&g_node_acc[(row0 + r) * DD + c];
        float* dstp = &sH[r * 513 + c];
        dstp[0] = v.x; dstp[1] = v.y; dstp[2] = v.z; dstp[3] = v.w;
    }
    // W2 -> sW
    for (int i = tid * 4; i < DD * DD; i += 1024)
        *(float4*)&sW[i] = *(const float4*)&W2[i];
    __syncthreads();

    const int rt = tid & 15, ct = tid >> 4;
    const int r0 = rt * 4, c0 = ct * 8, cp0 = c0 >> 1;
    const unsigned long long* sWu = (const unsigned long long*)sW;

    // ---- GEMM2: dot = acc @ W2 ----
    unsigned long long acc[4][4];
#pragma unroll
    for (int i = 0; i < 4; i++)
#pragma unroll
        for (int p = 0; p < 4; p++) acc[i][p] = 0ull;
    gemm_tile_k128(&sH[r0 * 513], 513, sWu, cp0, acc);

    // epilogue: h + (cn*dot + b2) -> sA
#pragma unroll
    for (int i = 0; i < 4; i++) {
        int rr = r0 + i;
        int gr = row0 + rr;
        float cn = sCn[rr];
#pragma unroll
        for (int p = 0; p < 4; p++) {
            float x, y;
            f2_unpack(acc[i][p], x, y);
            int c = c0 + 2 * p;
            float hx = 0.f, hy = 0.f;
            if (gr < NN) {
                float2 hv = *(const float2*)&h[gr * DD + c];
                hx = hv.x; hy = hv.y;
            }
            sA[rr * 129 + c]     = x * cn + __ldg(&b2[c]) + hx;
            sA[rr * 129 + c + 1] = y * cn + __ldg(&b2[c + 1]) + hy;
        }
    }
    __syncthreads();

    // ---- LN1 in place on sA ----
    {
        float gg[4], bb[4];
#pragma unroll
        for (int q = 0; q < 4; q++) {
            gg[q] = __ldg(&g1[lane + 32 * q]);
            bb[q] = __ldg(&be1[lane + 32 * q]);
        }
        for (int rr = warp * 8; rr < warp * 8 + 8; ++rr) {
            float* row = &sA[rr * 129];
            float v[4];
            float s = 0.f;
#pragma unroll
            for (int q = 0; q < 4; q++) { v[q] = row[lane + 32 * q]; s += v[q]; }
#pragma unroll
            for (int o = 16; o; o >>= 1) s += __shfl_xor_sync(0xffffffffu, s, o);
            float mu = s * 0.0078125f;
            float qs = 0.f;
#pragma unroll
            for (int q = 0; q < 4; q++) { v[q] -= mu; qs += v[q] * v[q]; }
#pragma unroll
            for (int o = 16; o; o >>= 1) qs += __shfl_xor_sync(0xffffffffu, qs, o);
            float inv = rsqrtf(qs * 0.0078125f + 1e-5f);
#pragma unroll
            for (int q = 0; q < 4; q++) row[lane + 32 * q] = v[q] * inv * gg[q] + bb[q];
        }
    }
    __syncthreads();

    // ---- FFN phase A: hid = relu(h1 @ W3 + b3), 4 n-chunks of 128 ----
    for (int nc = 0; nc < 4; nc++) {
        __syncthreads();
        for (int i = tid * 4; i < DD * DD; i += 1024) {
            int k = i >> 7, j = i & 127;
            *(float4*)&sW[k * 128 + j] = *(const float4*)&W3[k * HH + nc * 128 + j];
        }
        __syncthreads();
        unsigned long long bp[4];
#pragma unroll
        for (int p = 0; p < 4; p++) {
            float2 bv = *(const float2*)&b3[nc * 128 + c0 + 2 * p];
            bp[p] = f2_pack(bv.x, bv.y);
        }
        unsigned long long acc2[4][4];
#pragma unroll
        for (int i = 0; i < 4; i++)
#pragma unroll
            for (int p = 0; p < 4; p++) acc2[i][p] = bp[p];
        gemm_tile_k128(&sA[r0 * 129], 129, sWu, cp0, acc2);
#pragma unroll
        for (int i = 0; i < 4; i++) {
            int rbase = (r0 + i) * 513 + nc * 128 + c0;
#pragma unroll
            for (int p = 0; p < 4; p++) {
                float x, y;
                f2_unpack(acc2[i][p], x, y);
                sH[rbase + 2 * p]     = fmaxf(x, 0.f);
                sH[rbase + 2 * p + 1] = fmaxf(y, 0.f);
            }
        }
    }

    // ---- FFN phase B: out = hid @ W4 + b4, 4 k-chunks of 128 ----
    unsigned long long acc3[4][4];
#pragma unroll
    for (int p = 0; p < 4; p++) {
        float2 bv = *(const float2*)&b4[c0 + 2 * p];
        unsigned long long bp = f2_pack(bv.x, bv.y);
#pragma unroll
        for (int i = 0; i < 4; i++) acc3[i][p] = bp;
    }
    for (int kc = 0; kc < 4; kc++) {
        __syncthreads();
        for (int i = tid * 4; i < DD * DD; i += 1024)
            *(float4*)&sW[i] = *(const float4*)&W4[kc * 16384 + i];
        __syncthreads();
        gemm_tile_k128(&sH[r0 * 513 + kc * 128], 513, sWu, cp0, acc3);
    }
    __syncthreads();

    // epilogue: val = ffn + h1 -> sH (first 128 cols)
#pragma unroll
    for (int i = 0; i < 4; i++) {
        int rr = r0 + i;
#pragma unroll
        for (int p = 0; p < 4; p++) {
            float x, y;
            f2_unpack(acc3[i][p], x, y);
            int c = c0 + 2 * p;
            sH[rr * 513 + c]     = x + sA[rr * 129 + c];
            sH[rr * 513 + c + 1] = y + sA[rr * 129 + c + 1];
        }
    }
    __syncthreads();

    // ---- LN2 -> out ----
    {
        float gg[4], bb[4];
#pragma unroll
        for (int q = 0; q < 4; q++) {
            gg[q] = __ldg(&g2[lane + 32 * q]);
            bb[q] = __ldg(&be2[lane + 32 * q]);
        }
        for (int rr = warp * 8; rr < warp * 8 + 8; ++rr) {
            int gr = row0 + rr;
            float* row = &sH[rr * 513];
            float v[4];
            float s = 0.f;
#pragma unroll
            for (int q = 0; q < 4; q++) { v[q] = row[lane + 32 * q]; s += v[q]; }
#pragma unroll
            for (int o = 16; o; o >>= 1) s += __shfl_xor_sync(0xffffffffu, s, o);
            float mu = s * 0.0078125f;
            float qs = 0.f;
#pragma unroll
            for (int q = 0; q < 4; q++) { v[q] -= mu; qs += v[q] * v[q]; }
#pragma unroll
            for (int o = 16; o; o >>= 1) qs += __shfl_xor_sync(0xffffffffu, qs, o);
            float inv = rsqrtf(qs * 0.0078125f + 1e-5f);
            if (gr < NN) {
#pragma unroll
                for (int q = 0; q < 4; q++)
                    out[gr * DD + lane + 32 * q] = v[q] * inv * gg[q] + bb[q];
            }
        }
    }
}

// ---------------- launch ----------------
#define SMEM_GEMM1 ((64 * 129 + 128 * 128 + 64) * (int)sizeof(float))
#define SMEM_FUSED ((64 * 129 + 64 * 513 + 128 * 128 + 64) * (int)sizeof(float))

extern "C" void kernel_launch(void* const* d_in, const int* in_sizes, int n_in,
                              void* d_out, int out_size) {
    const float* h   = (const float*)d_in[0];
    const int*   src = (const int*)d_in[1];
    const int*   dst = (const int*)d_in[2];
    const float* W1  = (const float*)d_in[3];
    const float* b1  = (const float*)d_in[4];
    const float* W2  = (const float*)d_in[5];
    const float* b2  = (const float*)d_in[6];
    const float* W3  = (const float*)d_in[7];
    const float* b3  = (const float*)d_in[8];
    const float* W4  = (const float*)d_in[9];
    const float* b4  = (const float*)d_in[10];
    const float* g1  = (const float*)d_in[11];
    const float* be1 = (const float*)d_in[12];
    const float* g2  = (const float*)d_in[13];
    const float* be2 = (const float*)d_in[14];
    float* out = (float*)d_out;

    cudaFuncSetAttribute(k_gemm1, cudaFuncAttributeMaxDynamicSharedMemorySize, SMEM_GEMM1);
    cudaFuncSetAttribute(k_fused, cudaFuncAttributeMaxDynamicSharedMemorySize, SMEM_FUSED);

    k_zero<<<2048, 256>>>();
    k_deg<<<(NE + 255) / 256, 256>>>(src, dst);
    k_scatter1<<<NE / 8, 256>>>(h, src, dst);
    k_gemm1<<<(NH + 63) / 64, 256, SMEM_GEMM1>>>(W1, b1);
    k_scatter2<<<NE / 8, 256>>>(src, dst);
    k_fused<<<(NN + 63) / 64, 256, SMEM_FUSED>>>(h, W2, b2, W3, b3, W4, b4,
                                                 g1, be1, g2, be2, out);
}